// round 1
// baseline (speedup 1.0000x reference)
#include <cuda_runtime.h>
#include <cuda_bf16.h>
#include <math.h>

// Problem constants
#define BB 4
#define SS 2048
#define DD 1024

// Scratch (device globals — allocation-free per harness rules)
__device__ float g_q[(size_t)BB * SS * DD];
__device__ float g_k[(size_t)BB * SS * DD];
__device__ float g_v[(size_t)BB * SS * DD];
__device__ float g_s[(size_t)BB * SS * SS];

// ---------------------------------------------------------------------------
// SGEMM C = A @ B   (A row-major [M,K], B row-major [K,N], C row-major [M,N])
// 128x128 tile, BK=8, 256 threads, 8x8 per thread. All dims multiples of 128/8.
// blockIdx.z selects batch via strides.
// ---------------------------------------------------------------------------
__global__ __launch_bounds__(256, 2)
void sgemm_nn(const float* __restrict__ A, const float* __restrict__ B,
              float* __restrict__ C, int M, int N, int K,
              long long sA, long long sB, long long sC)
{
    A += (long long)blockIdx.z * sA;
    B += (long long)blockIdx.z * sB;
    C += (long long)blockIdx.z * sC;

    __shared__ float As[8][128];
    __shared__ float Bs[8][128];

    const int t  = threadIdx.x;
    const int tx = t & 15;
    const int ty = t >> 4;
    const int m0 = blockIdx.y * 128;
    const int n0 = blockIdx.x * 128;

    const int arow = t >> 1;           // 0..127
    const int acol = (t & 1) * 4;      // 0 or 4
    const int brow = t >> 5;           // 0..7
    const int bcol = (t & 31) * 4;     // 0..124

    float acc[8][8];
    #pragma unroll
    for (int i = 0; i < 8; i++)
        #pragma unroll
        for (int j = 0; j < 8; j++) acc[i][j] = 0.0f;

    for (int k0 = 0; k0 < K; k0 += 8) {
        float4 av = *(const float4*)(A + (long long)(m0 + arow) * K + k0 + acol);
        float4 bv = *(const float4*)(B + (long long)(k0 + brow) * N + n0 + bcol);
        As[acol + 0][arow] = av.x;
        As[acol + 1][arow] = av.y;
        As[acol + 2][arow] = av.z;
        As[acol + 3][arow] = av.w;
        *(float4*)(&Bs[brow][bcol]) = bv;
        __syncthreads();

        #pragma unroll
        for (int kk = 0; kk < 8; kk++) {
            float a[8], b[8];
            #pragma unroll
            for (int i = 0; i < 8; i++) a[i] = As[kk][ty * 8 + i];
            #pragma unroll
            for (int j = 0; j < 8; j++) b[j] = Bs[kk][tx * 8 + j];
            #pragma unroll
            for (int i = 0; i < 8; i++)
                #pragma unroll
                for (int j = 0; j < 8; j++)
                    acc[i][j] = fmaf(a[i], b[j], acc[i][j]);
        }
        __syncthreads();
    }

    #pragma unroll
    for (int i = 0; i < 8; i++) {
        long long row = (long long)(m0 + ty * 8 + i) * N + n0 + tx * 8;
        *(float4*)(C + row)     = make_float4(acc[i][0], acc[i][1], acc[i][2], acc[i][3]);
        *(float4*)(C + row + 4) = make_float4(acc[i][4], acc[i][5], acc[i][6], acc[i][7]);
    }
}

// ---------------------------------------------------------------------------
// SGEMM C = A @ B^T  (A [M,K], B [N,K], both row-major). Causal block skip:
// a tile whose entire key range is above the diagonal exits immediately.
// ---------------------------------------------------------------------------
__global__ __launch_bounds__(256, 2)
void sgemm_nt(const float* __restrict__ A, const float* __restrict__ B,
              float* __restrict__ C, int M, int N, int K,
              long long sA, long long sB, long long sC, int causal)
{
    const int m0 = blockIdx.y * 128;
    const int n0 = blockIdx.x * 128;
    if (causal && n0 > m0 + 127) return;   // fully-masked tile: never read later

    A += (long long)blockIdx.z * sA;
    B += (long long)blockIdx.z * sB;
    C += (long long)blockIdx.z * sC;

    __shared__ float As[8][128];
    __shared__ float Bs[8][128];

    const int t  = threadIdx.x;
    const int tx = t & 15;
    const int ty = t >> 4;

    const int arow = t >> 1;
    const int acol = (t & 1) * 4;

    float acc[8][8];
    #pragma unroll
    for (int i = 0; i < 8; i++)
        #pragma unroll
        for (int j = 0; j < 8; j++) acc[i][j] = 0.0f;

    for (int k0 = 0; k0 < K; k0 += 8) {
        float4 av = *(const float4*)(A + (long long)(m0 + arow) * K + k0 + acol);
        float4 bv = *(const float4*)(B + (long long)(n0 + arow) * K + k0 + acol);
        As[acol + 0][arow] = av.x;
        As[acol + 1][arow] = av.y;
        As[acol + 2][arow] = av.z;
        As[acol + 3][arow] = av.w;
        Bs[acol + 0][arow] = bv.x;
        Bs[acol + 1][arow] = bv.y;
        Bs[acol + 2][arow] = bv.z;
        Bs[acol + 3][arow] = bv.w;
        __syncthreads();

        #pragma unroll
        for (int kk = 0; kk < 8; kk++) {
            float a[8], b[8];
            #pragma unroll
            for (int i = 0; i < 8; i++) a[i] = As[kk][ty * 8 + i];
            #pragma unroll
            for (int j = 0; j < 8; j++) b[j] = Bs[kk][tx * 8 + j];
            #pragma unroll
            for (int i = 0; i < 8; i++)
                #pragma unroll
                for (int j = 0; j < 8; j++)
                    acc[i][j] = fmaf(a[i], b[j], acc[i][j]);
        }
        __syncthreads();
    }

    #pragma unroll
    for (int i = 0; i < 8; i++) {
        long long row = (long long)(m0 + ty * 8 + i) * N + n0 + tx * 8;
        *(float4*)(C + row)     = make_float4(acc[i][0], acc[i][1], acc[i][2], acc[i][3]);
        *(float4*)(C + row + 4) = make_float4(acc[i][4], acc[i][5], acc[i][6], acc[i][7]);
    }
}

// ---------------------------------------------------------------------------
// Causal row softmax over scores (scale applied inside). One block per row.
// Writes the FULL row: softmax values for j<=i, zeros for j>i, so the
// following attn@V GEMM can be dense.
// ---------------------------------------------------------------------------
__global__ __launch_bounds__(256)
void softmax_causal(float* __restrict__ Sc, int S, float scale)
{
    const long long row = blockIdx.x;          // b*S + i
    const int i = (int)(row % S);
    float* p = Sc + row * (long long)S;
    const int L = i + 1;

    const int tid  = threadIdx.x;
    const int lane = tid & 31;
    const int wid  = tid >> 5;
    __shared__ float red[32];

    // ---- pass 1: max over valid entries ----
    float mx = -INFINITY;
    for (int j = tid; j < L; j += 256) mx = fmaxf(mx, p[j]);
    #pragma unroll
    for (int o = 16; o; o >>= 1) mx = fmaxf(mx, __shfl_xor_sync(0xffffffffu, mx, o));
    if (lane == 0) red[wid] = mx;
    __syncthreads();
    if (tid == 0) {
        float m = red[0];
        #pragma unroll
        for (int w = 1; w < 8; w++) m = fmaxf(m, red[w]);
        red[0] = m;
    }
    __syncthreads();
    mx = red[0];
    __syncthreads();

    // ---- pass 2: exp + sum ----
    float sum = 0.0f;
    for (int j = tid; j < L; j += 256) {
        float e = expf((p[j] - mx) * scale);
        p[j] = e;
        sum += e;
    }
    #pragma unroll
    for (int o = 16; o; o >>= 1) sum += __shfl_xor_sync(0xffffffffu, sum, o);
    if (lane == 0) red[wid] = sum;
    __syncthreads();
    if (tid == 0) {
        float s = red[0];
        #pragma unroll
        for (int w = 1; w < 8; w++) s += red[w];
        red[0] = s;
    }
    __syncthreads();
    const float inv = 1.0f / red[0];

    // ---- pass 3: normalize + zero masked tail ----
    for (int j = tid; j < L; j += 256) p[j] *= inv;
    for (int j = L + tid; j < S; j += 256) p[j] = 0.0f;
}

// ---------------------------------------------------------------------------
extern "C" void kernel_launch(void* const* d_in, const int* in_sizes, int n_in,
                              void* d_out, int out_size)
{
    (void)in_sizes; (void)n_in; (void)out_size;
    const float* x  = (const float*)d_in[0];
    const float* Wq = (const float*)d_in[1];
    const float* Wk = (const float*)d_in[2];
    const float* Wv = (const float*)d_in[3];
    float* out = (float*)d_out;

    float *q, *k, *v, *s;
    cudaGetSymbolAddress((void**)&q, g_q);
    cudaGetSymbolAddress((void**)&k, g_k);
    cudaGetSymbolAddress((void**)&v, g_v);
    cudaGetSymbolAddress((void**)&s, g_s);

    const int B = BB, S = SS, D = DD;
    dim3 blk(256);

    // 1) QKV projections: [8192,1024] @ [1024,1024]
    dim3 g1(D / 128, (B * S) / 128, 1);
    sgemm_nn<<<g1, blk>>>(x, Wq, q, B * S, D, D, 0, 0, 0);
    sgemm_nn<<<g1, blk>>>(x, Wk, k, B * S, D, D, 0, 0, 0);
    sgemm_nn<<<g1, blk>>>(x, Wv, v, B * S, D, D, 0, 0, 0);

    // 2) scores = Q @ K^T per batch (causal tile skip)
    dim3 g2(S / 128, S / 128, B);
    sgemm_nt<<<g2, blk>>>(q, k, s, S, S, D,
                          (long long)S * D, (long long)S * D, (long long)S * S, 1);

    // 3) causal softmax with scale 1/sqrt(D) = 1/32
    softmax_causal<<<B * S, 256>>>(s, S, 0.03125f);

    // 4) out = attn @ V per batch
    dim3 g3(D / 128, S / 128, B);
    sgemm_nn<<<g3, blk>>>(s, v, out, S, D, S,
                          (long long)S * S, (long long)S * D, (long long)S * D);
}

// round 2
// speedup vs baseline: 1.7984x; 1.7984x over previous
#include <cuda_runtime.h>
#include <cuda_bf16.h>
#include <cstdint>
#include <math.h>

#define BB 4
#define SS 2048
#define DD 1024

// ---------------------------------------------------------------------------
// Scratch (device globals — allocation-free per harness rules)
// ---------------------------------------------------------------------------
__device__ __nv_bfloat16 g_x3 [(size_t)BB * SS * 3 * DD];           // x, pattern X  [8192][3072]
__device__ __nv_bfloat16 g_wq3t[(size_t)DD * 3 * DD];               // Wq^T, pattern Y [1024][3072]
__device__ __nv_bfloat16 g_wk3t[(size_t)DD * 3 * DD];
__device__ __nv_bfloat16 g_wv3t[(size_t)DD * 3 * DD];
__device__ float         g_qf  [(size_t)BB * SS * DD];
__device__ float         g_kf  [(size_t)BB * SS * DD];
__device__ float         g_vf  [(size_t)BB * SS * DD];
__device__ __nv_bfloat16 g_q3  [(size_t)BB * SS * 3 * DD];          // pattern X
__device__ __nv_bfloat16 g_k3  [(size_t)BB * SS * 3 * DD];          // pattern Y
__device__ __nv_bfloat16 g_vt3 [(size_t)BB * DD * 3 * SS];          // v^T, pattern Y [b][1024][6144]
__device__ float         g_s   [(size_t)BB * SS * SS];              // raw scores fp32
__device__ __nv_bfloat16 g_a3  [(size_t)BB * SS * 3 * SS];          // attn, pattern X [b][2048][6144]

// ---------------------------------------------------------------------------
// Helpers
// ---------------------------------------------------------------------------
__device__ __forceinline__ void cp16(uint32_t dst, const void* src) {
    asm volatile("cp.async.cg.shared.global [%0], [%1], 16;\n" :: "r"(dst), "l"(src));
}
__device__ __forceinline__ void cp_commit() { asm volatile("cp.async.commit_group;\n"); }

__device__ __forceinline__ void mma_bf16(float c[4], const uint32_t a[4], const uint32_t b[2]) {
    asm volatile(
        "mma.sync.aligned.m16n8k16.row.col.f32.bf16.bf16.f32 "
        "{%0,%1,%2,%3}, {%4,%5,%6,%7}, {%8,%9}, {%0,%1,%2,%3};\n"
        : "+f"(c[0]), "+f"(c[1]), "+f"(c[2]), "+f"(c[3])
        : "r"(a[0]), "r"(a[1]), "r"(a[2]), "r"(a[3]), "r"(b[0]), "r"(b[1]));
}

// ---------------------------------------------------------------------------
// bf16 GEMM, both operands K-major:  C[m][n] = sum_k A[m][k] * B[n][k]
// Block 128x128xBK32, 256 threads, 8 warps (4m x 2n), warp tile 32x64.
// SMEM rows padded to 40 bf16 (20 words) -> conflict-free fragment loads.
// ---------------------------------------------------------------------------
__global__ __launch_bounds__(256, 2)
void gemm_bf16_tn(const __nv_bfloat16* __restrict__ A,
                  const __nv_bfloat16* __restrict__ B,
                  float* __restrict__ C,
                  int M, int N, int Kp,
                  long long strA, long long strB, long long strC, int causal)
{
    const int m0 = blockIdx.y * 128;
    const int n0 = blockIdx.x * 128;
    if (causal && n0 > m0 + 127) return;
    const int z = blockIdx.z;

    const __nv_bfloat16* Ag = A + (long long)z * strA + (size_t)m0 * Kp;
    const __nv_bfloat16* Bg = B + (long long)z * strB + (size_t)n0 * Kp;
    float* Cg = C + (long long)z * strC;

    __shared__ uint32_t sm[2][2][128 * 20];   // [stage][A/B][row*20 + word]

    const int tid  = threadIdx.x;
    const int lane = tid & 31;
    const int wid  = tid >> 5;
    const int g    = lane >> 2;   // 0..7
    const int tq   = lane & 3;    // 0..3
    const int wm   = wid >> 1;    // 0..3  (m tile)
    const int wn   = wid & 1;     // 0..1  (n tile)

    const int crow = tid >> 1;    // copy row 0..127
    const int cseg = tid & 1;     // half-row (16 bf16)

    const uint32_t smem0 = (uint32_t)__cvta_generic_to_shared(&sm[0][0][0]);
    const uint32_t dA_off = (uint32_t)((crow * 20 + cseg * 8) * 4);

    float acc[2][8][4];
    #pragma unroll
    for (int i = 0; i < 2; i++)
        #pragma unroll
        for (int j = 0; j < 8; j++)
            #pragma unroll
            for (int q = 0; q < 4; q++) acc[i][j][q] = 0.0f;

    const int nC = Kp >> 5;   // chunks of 32

    // prefetch chunk 0 -> stage 0
    {
        const __nv_bfloat16* a = Ag + (size_t)crow * Kp + cseg * 16;
        const __nv_bfloat16* b = Bg + (size_t)crow * Kp + cseg * 16;
        uint32_t da = smem0 + dA_off;
        uint32_t db = da + 10240;
        cp16(da, a); cp16(da + 16, a + 8);
        cp16(db, b); cp16(db + 16, b + 8);
        cp_commit();
    }

    for (int c = 0; c < nC; ++c) {
        const int cur = c & 1;
        if (c + 1 < nC) {
            const int kc = (c + 1) << 5;
            const __nv_bfloat16* a = Ag + (size_t)crow * Kp + kc + cseg * 16;
            const __nv_bfloat16* b = Bg + (size_t)crow * Kp + kc + cseg * 16;
            uint32_t da = smem0 + ((c + 1) & 1) * 20480u + dA_off;
            uint32_t db = da + 10240;
            cp16(da, a); cp16(da + 16, a + 8);
            cp16(db, b); cp16(db + 16, b + 8);
            cp_commit();
            asm volatile("cp.async.wait_group 1;\n");
        } else {
            asm volatile("cp.async.wait_group 0;\n");
        }
        __syncthreads();

        const uint32_t* Aw = &sm[cur][0][0];
        const uint32_t* Bw = &sm[cur][1][0];

        #pragma unroll
        for (int ks = 0; ks < 2; ks++) {
            const int kw = ks * 8;
            uint32_t afr[2][4], bfr[8][2];
            #pragma unroll
            for (int im = 0; im < 2; im++) {
                const int r = wm * 32 + im * 16;
                afr[im][0] = Aw[(r + g)     * 20 + kw + tq];
                afr[im][1] = Aw[(r + g + 8) * 20 + kw + tq];
                afr[im][2] = Aw[(r + g)     * 20 + kw + tq + 4];
                afr[im][3] = Aw[(r + g + 8) * 20 + kw + tq + 4];
            }
            #pragma unroll
            for (int jn = 0; jn < 8; jn++) {
                const int cb = wn * 64 + jn * 8 + g;
                bfr[jn][0] = Bw[cb * 20 + kw + tq];
                bfr[jn][1] = Bw[cb * 20 + kw + tq + 4];
            }
            #pragma unroll
            for (int im = 0; im < 2; im++)
                #pragma unroll
                for (int jn = 0; jn < 8; jn++)
                    mma_bf16(acc[im][jn], afr[im], bfr[jn]);
        }
        __syncthreads();
    }

    // epilogue: fp32 store
    #pragma unroll
    for (int im = 0; im < 2; im++) {
        #pragma unroll
        for (int jn = 0; jn < 8; jn++) {
            const int r  = m0 + wm * 32 + im * 16 + g;
            const int cc = n0 + wn * 64 + jn * 8 + 2 * tq;
            *(float2*)(Cg + (size_t)r * N + cc)       = make_float2(acc[im][jn][0], acc[im][jn][1]);
            *(float2*)(Cg + (size_t)(r + 8) * N + cc) = make_float2(acc[im][jn][2], acc[im][jn][3]);
        }
    }
}

// ---------------------------------------------------------------------------
// fp32 -> tripled-K bf16, same row layout. mode 0 = pattern X [hi,lo,hi]
// (A operand), mode 1 = pattern Y [hi,hi,lo] (B operand).
// ---------------------------------------------------------------------------
__global__ __launch_bounds__(256)
void conv_split(const float* __restrict__ src, __nv_bfloat16* __restrict__ dst,
                int K, int mode)
{
    const long long idx = (long long)blockIdx.x * 256 + threadIdx.x;
    const long long m = idx / K;
    const int j = (int)(idx % K);
    const float v = src[idx];
    const __nv_bfloat16 h = __float2bfloat16(v);
    const __nv_bfloat16 l = __float2bfloat16(v - __bfloat162float(h));
    __nv_bfloat16* o = dst + m * 3LL * K;
    if (mode == 0) { o[j] = h; o[K + j] = l; o[2 * K + j] = h; }
    else           { o[j] = h; o[K + j] = h; o[2 * K + j] = l; }
}

// ---------------------------------------------------------------------------
// fp32 [R][C] -> transposed tripled-K bf16 [C][3R], pattern Y [hi,hi,lo].
// ---------------------------------------------------------------------------
__global__ __launch_bounds__(256)
void transposeY(const float* __restrict__ src, __nv_bfloat16* __restrict__ dst,
                int R, int C, long long sSrc, long long sDst)
{
    __shared__ float tile[32][33];
    src += (long long)blockIdx.z * sSrc;
    dst += (long long)blockIdx.z * sDst;
    const int r0 = blockIdx.y * 32, c0 = blockIdx.x * 32;
    const int tx = threadIdx.x & 31;
    const int ty = threadIdx.x >> 5;     // 0..7

    #pragma unroll
    for (int dy = 0; dy < 32; dy += 8)
        tile[ty + dy][tx] = src[(size_t)(r0 + ty + dy) * C + c0 + tx];
    __syncthreads();

    #pragma unroll
    for (int dy = 0; dy < 32; dy += 8) {
        const int c = c0 + ty + dy;
        const int r = r0 + tx;
        const float v = tile[tx][ty + dy];
        const __nv_bfloat16 h = __float2bfloat16(v);
        const __nv_bfloat16 l = __float2bfloat16(v - __bfloat162float(h));
        __nv_bfloat16* o = dst + (size_t)c * 3 * R;
        o[r] = h; o[R + r] = h; o[2 * R + r] = l;
    }
}

// ---------------------------------------------------------------------------
// Causal softmax over raw scores, emitting tripled-K bf16 attn (pattern X)
// with zeros in the masked region. One block per (b,i) row.
// ---------------------------------------------------------------------------
__global__ __launch_bounds__(256)
void softmax_attn3(const float* __restrict__ Sc, __nv_bfloat16* __restrict__ A3,
                   int S, float scale)
{
    const long long row = blockIdx.x;            // b*S + i
    const int i = (int)(row % S);
    const float* p = Sc + row * (long long)S;
    __nv_bfloat16* out = A3 + row * (long long)(3 * S);
    const int L = i + 1;

    const int tid  = threadIdx.x;
    const int lane = tid & 31;
    const int wid  = tid >> 5;
    __shared__ float red[32];

    float mx = -INFINITY;
    for (int j = tid; j < L; j += 256) mx = fmaxf(mx, p[j]);
    #pragma unroll
    for (int o = 16; o; o >>= 1) mx = fmaxf(mx, __shfl_xor_sync(0xffffffffu, mx, o));
    if (lane == 0) red[wid] = mx;
    __syncthreads();
    if (tid == 0) {
        float m = red[0];
        #pragma unroll
        for (int w = 1; w < 8; w++) m = fmaxf(m, red[w]);
        red[0] = m;
    }
    __syncthreads();
    mx = red[0];
    __syncthreads();

    float sum = 0.0f;
    for (int j = tid; j < L; j += 256) sum += expf((p[j] - mx) * scale);
    #pragma unroll
    for (int o = 16; o; o >>= 1) sum += __shfl_xor_sync(0xffffffffu, sum, o);
    if (lane == 0) red[wid] = sum;
    __syncthreads();
    if (tid == 0) {
        float s = red[0];
        #pragma unroll
        for (int w = 1; w < 8; w++) s += red[w];
        red[0] = s;
    }
    __syncthreads();
    const float inv = 1.0f / red[0];

    for (int j = tid; j < L; j += 256) {
        const float v = expf((p[j] - mx) * scale) * inv;
        const __nv_bfloat16 h = __float2bfloat16(v);
        const __nv_bfloat16 l = __float2bfloat16(v - __bfloat162float(h));
        out[j] = h; out[S + j] = l; out[2 * S + j] = h;
    }
    const __nv_bfloat16 zero = __float2bfloat16(0.0f);
    for (int j = L + tid; j < S; j += 256) {
        out[j] = zero; out[S + j] = zero; out[2 * S + j] = zero;
    }
}

// ---------------------------------------------------------------------------
extern "C" void kernel_launch(void* const* d_in, const int* in_sizes, int n_in,
                              void* d_out, int out_size)
{
    (void)in_sizes; (void)n_in; (void)out_size;
    const float* x  = (const float*)d_in[0];
    const float* Wq = (const float*)d_in[1];
    const float* Wk = (const float*)d_in[2];
    const float* Wv = (const float*)d_in[3];
    float* out = (float*)d_out;

    __nv_bfloat16 *x3, *wq3t, *wk3t, *wv3t, *q3, *k3, *vt3, *a3;
    float *qf, *kf, *vf, *s;
    cudaGetSymbolAddress((void**)&x3,   g_x3);
    cudaGetSymbolAddress((void**)&wq3t, g_wq3t);
    cudaGetSymbolAddress((void**)&wk3t, g_wk3t);
    cudaGetSymbolAddress((void**)&wv3t, g_wv3t);
    cudaGetSymbolAddress((void**)&qf,   g_qf);
    cudaGetSymbolAddress((void**)&kf,   g_kf);
    cudaGetSymbolAddress((void**)&vf,   g_vf);
    cudaGetSymbolAddress((void**)&q3,   g_q3);
    cudaGetSymbolAddress((void**)&k3,   g_k3);
    cudaGetSymbolAddress((void**)&vt3,  g_vt3);
    cudaGetSymbolAddress((void**)&s,    g_s);
    cudaGetSymbolAddress((void**)&a3,   g_a3);

    const int B = BB, S = SS, D = DD;
    const long long MS = (long long)B * S;   // 8192

    // 1) operand conversion
    conv_split<<<(int)(MS * D / 256), 256>>>(x, x3, D, 0);
    {
        dim3 tg(D / 32, D / 32, 1);
        transposeY<<<tg, 256>>>(Wq, wq3t, D, D, 0, 0);
        transposeY<<<tg, 256>>>(Wk, wk3t, D, D, 0, 0);
        transposeY<<<tg, 256>>>(Wv, wv3t, D, D, 0, 0);
    }

    // 2) QKV projections: [8192][3072] x [1024][3072]^T
    {
        dim3 gg(D / 128, (int)(MS / 128), 1);
        gemm_bf16_tn<<<gg, 256>>>(x3, wq3t, qf, (int)MS, D, 3 * D, 0, 0, 0, 0);
        gemm_bf16_tn<<<gg, 256>>>(x3, wk3t, kf, (int)MS, D, 3 * D, 0, 0, 0, 0);
        gemm_bf16_tn<<<gg, 256>>>(x3, wv3t, vf, (int)MS, D, 3 * D, 0, 0, 0, 0);
    }

    // 3) split q/k, transpose-split v
    conv_split<<<(int)(MS * D / 256), 256>>>(qf, q3, D, 0);
    conv_split<<<(int)(MS * D / 256), 256>>>(kf, k3, D, 1);
    {
        dim3 tg(D / 32, S / 32, B);
        transposeY<<<tg, 256>>>(vf, vt3, S, D,
                                (long long)S * D, (long long)D * 3 * S);
    }

    // 4) scores = Q K^T per batch (causal tile skip), K' = 3D
    {
        dim3 gg(S / 128, S / 128, B);
        gemm_bf16_tn<<<gg, 256>>>(q3, k3, s, S, S, 3 * D,
                                  (long long)S * 3 * D, (long long)S * 3 * D,
                                  (long long)S * S, 1);
    }

    // 5) softmax -> tripled bf16 attn
    softmax_attn3<<<B * S, 256>>>(s, a3, S, 0.03125f);

    // 6) out = attn @ V, K' = 3S
    {
        dim3 gg(D / 128, S / 128, B);
        gemm_bf16_tn<<<gg, 256>>>(a3, vt3, out, S, D, 3 * S,
                                  (long long)S * 3 * S, (long long)D * 3 * S,
                                  (long long)S * D, 0);
    }
}

// round 4
// speedup vs baseline: 1.9588x; 1.0892x over previous
#include <cuda_runtime.h>
#include <cuda_bf16.h>
#include <cstdint>
#include <math.h>

#define BB 4
#define SS 2048
#define DD 1024

// ---------------------------------------------------------------------------
// Scratch (device globals — allocation-free per harness rules)
// All bf16 operand buffers use [hi | lo] layout: row length = 2*Kphys.
// ---------------------------------------------------------------------------
__device__ __nv_bfloat16 g_x3 [(size_t)BB * SS * 2 * DD];   // x split      [8192][2048]
__device__ __nv_bfloat16 g_wqt[(size_t)DD * 2 * DD];        // Wq^T split   [1024][2048]
__device__ __nv_bfloat16 g_wkt[(size_t)DD * 2 * DD];
__device__ __nv_bfloat16 g_wvt[(size_t)DD * 2 * DD];
__device__ __nv_bfloat16 g_q3 [(size_t)BB * SS * 2 * DD];   // q split
__device__ __nv_bfloat16 g_k3 [(size_t)BB * SS * 2 * DD];   // k split
__device__ float         g_vf [(size_t)BB * SS * DD];       // v fp32
__device__ __nv_bfloat16 g_vt3[(size_t)BB * DD * 2 * SS];   // v^T split  [b][1024][4096]
__device__ float         g_s  [(size_t)BB * SS * SS];       // raw scores fp32
__device__ __nv_bfloat16 g_a3 [(size_t)BB * SS * 2 * SS];   // attn split [b][2048][4096]

// ---------------------------------------------------------------------------
// PTX helpers (compute_103-safe: cp.async, ldmatrix, mma.sync only)
// ---------------------------------------------------------------------------
__device__ __forceinline__ void cp16(uint32_t dst, const void* src) {
    asm volatile("cp.async.cg.shared.global [%0], [%1], 16;\n" :: "r"(dst), "l"(src));
}
__device__ __forceinline__ uint32_t swz64(uint32_t off) { return off ^ ((off >> 3) & 0x30); }

__device__ __forceinline__ void ldsm4(uint32_t& r0, uint32_t& r1, uint32_t& r2, uint32_t& r3,
                                      uint32_t addr) {
    asm volatile("ldmatrix.sync.aligned.m8n8.x4.shared.b16 {%0,%1,%2,%3}, [%4];"
                 : "=r"(r0), "=r"(r1), "=r"(r2), "=r"(r3) : "r"(addr));
}

__device__ __forceinline__ void mma_bf16(float c[4], const uint32_t a[4], const uint32_t b0,
                                         const uint32_t b1) {
    asm volatile(
        "mma.sync.aligned.m16n8k16.row.col.f32.bf16.bf16.f32 "
        "{%0,%1,%2,%3}, {%4,%5,%6,%7}, {%8,%9}, {%0,%1,%2,%3};\n"
        : "+f"(c[0]), "+f"(c[1]), "+f"(c[2]), "+f"(c[3])
        : "r"(a[0]), "r"(a[1]), "r"(a[2]), "r"(a[3]), "r"(b0), "r"(b1));
}

// ---------------------------------------------------------------------------
// mma.sync GEMM:  C[m][n] = sum over 3 logical passes of A[m][pa+k]*B[n][pb+k]
// A,B bf16 K-major rows of length 2*Kphys. CTA tile 128x128, BK=32.
// 128 threads = 4 warps of 64x64, ldmatrix.x4 fragments, 4-stage cp.async.
// causal: 0 none, 1 tile-skip (scores), 2 K-clamp at diagonal (attn@V).
// mode 0: C fp32 (row len N_C). mode 1: C split-bf16 (row len 2*N_C, hi|lo).
// ---------------------------------------------------------------------------
#define NSTAGE 4
#define STAGE_BYTES 16384            // A 8KB + B 8KB
#define GEMM_SMEM (NSTAGE * STAGE_BYTES)

__global__ __launch_bounds__(128, 2)
void gemm_mma(const __nv_bfloat16* __restrict__ A, const __nv_bfloat16* __restrict__ B,
              void* __restrict__ Cv, int N_C, int Kphys, int cpp,
              int pa0, int pa1, int pa2, int pb0, int pb1, int pb2,
              long long strA, long long strB, long long strC, int causal, int mode)
{
    const int m0 = blockIdx.y * 128;
    const int n0 = blockIdx.x * 128;
    if (causal == 1 && n0 > m0 + 127) return;

    extern __shared__ __align__(1024) char smem[];
    const uint32_t base0 = (uint32_t)__cvta_generic_to_shared(smem);

    const int tid  = threadIdx.x;
    const int wid  = tid >> 5;
    const int lane = tid & 31;
    const int wm   = wid >> 1;      // 0..1
    const int wn   = wid & 1;       // 0..1
    const int z    = blockIdx.z;

    const __nv_bfloat16* Ag = A + (long long)z * strA;
    const __nv_bfloat16* Bg = B + (long long)z * strB;
    const int rowL = 2 * Kphys;

    const int cpp_eff = (causal == 2) ? min(cpp, (m0 >> 5) + 4) : cpp;
    const int nC = 3 * cpp_eff;

    // fragment ldmatrix address offsets (within a stage), precomputed
    const int mo  = ((lane >> 3) & 1) * 8 + (lane & 7);
    const int akb = ((lane >> 4) & 1) * 16;
    const int no  = ((lane >> 4) & 1) * 8 + (lane & 7);
    const int bkb = ((lane >> 3) & 1) * 16;
    uint32_t aoff[2][4], boff[2][4];
    #pragma unroll
    for (int ks = 0; ks < 2; ks++)
        #pragma unroll
        for (int f = 0; f < 4; f++) {
            aoff[ks][f] = swz64((uint32_t)((wm * 64 + f * 16 + mo) * 64 + ks * 32 + akb));
            boff[ks][f] = swz64((uint32_t)((wn * 64 + f * 16 + no) * 64 + ks * 32 + bkb));
        }

    float acc[4][8][4];
    #pragma unroll
    for (int i = 0; i < 4; i++)
        #pragma unroll
        for (int j = 0; j < 8; j++)
            #pragma unroll
            for (int q = 0; q < 4; q++) acc[i][j][q] = 0.0f;

    // chunk loader: thread t loads A row m0+t and B row n0+t (64B each)
    auto load_chunk = [&](int c) {
        const int st = c & (NSTAGE - 1);
        const int p  = c / cpp_eff;
        const int ip = c - p * cpp_eff;
        const int pA = (p == 0) ? pa0 : ((p == 1) ? pa1 : pa2);
        const int pB = (p == 0) ? pb0 : ((p == 1) ? pb1 : pb2);
        const uint32_t aBase = base0 + st * STAGE_BYTES;
        const uint32_t bBase = aBase + 8192;
        const __nv_bfloat16* as = Ag + (size_t)(m0 + tid) * rowL + pA + ip * 32;
        const __nv_bfloat16* bs = Bg + (size_t)(n0 + tid) * rowL + pB + ip * 32;
        const uint32_t ro = (uint32_t)tid * 64;
        #pragma unroll
        for (int s4 = 0; s4 < 4; s4++) {
            cp16(aBase + swz64(ro + s4 * 16), as + s4 * 8);
            cp16(bBase + swz64(ro + s4 * 16), bs + s4 * 8);
        }
        asm volatile("cp.async.commit_group;\n");
    };

    for (int i = 0; i < 3 && i < nC; i++) load_chunk(i);

    for (int c = 0; c < nC; ++c) {
        const int pend = (nC - c - 1 < 2) ? (nC - c - 1) : 2;
        if (pend == 2)      asm volatile("cp.async.wait_group 2;\n" ::: "memory");
        else if (pend == 1) asm volatile("cp.async.wait_group 1;\n" ::: "memory");
        else                asm volatile("cp.async.wait_group 0;\n" ::: "memory");
        __syncthreads();

        if (c + 3 < nC) load_chunk(c + 3);

        const uint32_t aB = base0 + (c & (NSTAGE - 1)) * STAGE_BYTES;
        const uint32_t bB = aB + 8192;

        #pragma unroll
        for (int ks = 0; ks < 2; ks++) {
            uint32_t af[4][4], bf[4][4];
            #pragma unroll
            for (int f = 0; f < 4; f++)
                ldsm4(af[f][0], af[f][1], af[f][2], af[f][3], aB + aoff[ks][f]);
            #pragma unroll
            for (int f = 0; f < 4; f++)
                ldsm4(bf[f][0], bf[f][1], bf[f][2], bf[f][3], bB + boff[ks][f]);
            #pragma unroll
            for (int im = 0; im < 4; im++)
                #pragma unroll
                for (int jn = 0; jn < 8; jn++)
                    mma_bf16(acc[im][jn], af[im],
                             bf[jn >> 1][(jn & 1) * 2], bf[jn >> 1][(jn & 1) * 2 + 1]);
        }
    }

    // epilogue
    #pragma unroll
    for (int im = 0; im < 4; im++) {
        const int r = m0 + wm * 64 + im * 16 + (lane >> 2);
        #pragma unroll
        for (int jn = 0; jn < 8; jn++) {
            const int cc = n0 + wn * 64 + jn * 8 + (lane & 3) * 2;
            if (mode == 0) {
                float* Cg = (float*)Cv + (long long)z * strC;
                *(float2*)(Cg + (size_t)r * N_C + cc)       = make_float2(acc[im][jn][0], acc[im][jn][1]);
                *(float2*)(Cg + (size_t)(r + 8) * N_C + cc) = make_float2(acc[im][jn][2], acc[im][jn][3]);
            } else {
                __nv_bfloat16* Cg = (__nv_bfloat16*)Cv + (long long)z * strC;
                #pragma unroll
                for (int hr = 0; hr < 2; hr++) {
                    const float v0 = acc[im][jn][hr * 2];
                    const float v1 = acc[im][jn][hr * 2 + 1];
                    const __nv_bfloat16 h0 = __float2bfloat16(v0);
                    const __nv_bfloat16 l0 = __float2bfloat16(v0 - __bfloat162float(h0));
                    const __nv_bfloat16 h1 = __float2bfloat16(v1);
                    const __nv_bfloat16 l1 = __float2bfloat16(v1 - __bfloat162float(h1));
                    __nv_bfloat16* row = Cg + (size_t)(r + hr * 8) * (2 * N_C);
                    *(__nv_bfloat162*)(row + cc)       = __halves2bfloat162(h0, h1);
                    *(__nv_bfloat162*)(row + N_C + cc) = __halves2bfloat162(l0, l1);
                }
            }
        }
    }
}

// ---------------------------------------------------------------------------
// fp32 -> [hi | lo] bf16 split, same row layout (row len 2K).
// ---------------------------------------------------------------------------
__global__ __launch_bounds__(256)
void conv_split2(const float* __restrict__ src, __nv_bfloat16* __restrict__ dst, int K)
{
    const long long idx = (long long)blockIdx.x * 256 + threadIdx.x;
    const long long m = idx / K;
    const int j = (int)(idx % K);
    const float v = src[idx];
    const __nv_bfloat16 h = __float2bfloat16(v);
    const __nv_bfloat16 l = __float2bfloat16(v - __bfloat162float(h));
    __nv_bfloat16* o = dst + m * 2LL * K;
    o[j] = h; o[K + j] = l;
}

// ---------------------------------------------------------------------------
// fp32 [R][C] -> transposed split bf16 [C][2R] (hi | lo)
// ---------------------------------------------------------------------------
__global__ __launch_bounds__(256)
void transposeY2(const float* __restrict__ src, __nv_bfloat16* __restrict__ dst,
                 int R, int C, long long sSrc, long long sDst)
{
    __shared__ float tile[32][33];
    src += (long long)blockIdx.z * sSrc;
    dst += (long long)blockIdx.z * sDst;
    const int r0 = blockIdx.y * 32, c0 = blockIdx.x * 32;
    const int tx = threadIdx.x & 31;
    const int ty = threadIdx.x >> 5;

    #pragma unroll
    for (int dy = 0; dy < 32; dy += 8)
        tile[ty + dy][tx] = src[(size_t)(r0 + ty + dy) * C + c0 + tx];
    __syncthreads();

    #pragma unroll
    for (int dy = 0; dy < 32; dy += 8) {
        const int c = c0 + ty + dy;
        const int r = r0 + tx;
        const float v = tile[tx][ty + dy];
        const __nv_bfloat16 h = __float2bfloat16(v);
        const __nv_bfloat16 l = __float2bfloat16(v - __bfloat162float(h));
        __nv_bfloat16* o = dst + (size_t)c * 2 * R;
        o[r] = h; o[R + r] = l;
    }
}

// ---------------------------------------------------------------------------
// Causal softmax emitting split bf16 attn [hi | lo]. Zero-fills only up to the
// 128-row diagonal-block boundary (the AV GEMM K-clamp never reads past it).
// ---------------------------------------------------------------------------
__global__ __launch_bounds__(256)
void softmax2(const float* __restrict__ Sc, __nv_bfloat16* __restrict__ A3,
              int S, float scale)
{
    const long long row = blockIdx.x;            // b*S + i
    const int i = (int)(row % S);
    const float* p = Sc + row * (long long)S;
    __nv_bfloat16* out = A3 + row * (long long)(2 * S);
    const int L = i + 1;
    const int Lz = ((i >> 7) + 1) << 7;          // diagonal-block end

    const int tid  = threadIdx.x;
    const int lane = tid & 31;
    const int wid  = tid >> 5;
    __shared__ float red[32];

    float mx = -INFINITY;
    for (int j = tid; j < L; j += 256) mx = fmaxf(mx, p[j]);
    #pragma unroll
    for (int o = 16; o; o >>= 1) mx = fmaxf(mx, __shfl_xor_sync(0xffffffffu, mx, o));
    if (lane == 0) red[wid] = mx;
    __syncthreads();
    if (tid == 0) {
        float m = red[0];
        #pragma unroll
        for (int w = 1; w < 8; w++) m = fmaxf(m, red[w]);
        red[0] = m;
    }
    __syncthreads();
    mx = red[0];
    __syncthreads();

    float e[8];
    float sum = 0.0f;
    int cnt = 0;
    for (int j = tid; j < L; j += 256) {
        const float ev = __expf((p[j] - mx) * scale);
        e[cnt++] = ev;
        sum += ev;
    }
    #pragma unroll
    for (int o = 16; o; o >>= 1) sum += __shfl_xor_sync(0xffffffffu, sum, o);
    if (lane == 0) red[wid] = sum;
    __syncthreads();
    if (tid == 0) {
        float s = red[0];
        #pragma unroll
        for (int w = 1; w < 8; w++) s += red[w];
        red[0] = s;
    }
    __syncthreads();
    const float inv = 1.0f / red[0];

    cnt = 0;
    for (int j = tid; j < L; j += 256) {
        const float v = e[cnt++] * inv;
        const __nv_bfloat16 h = __float2bfloat16(v);
        const __nv_bfloat16 l = __float2bfloat16(v - __bfloat162float(h));
        out[j] = h; out[S + j] = l;
    }
    const __nv_bfloat16 zero = __float2bfloat16(0.0f);
    for (int j = L + tid; j < Lz; j += 256) {
        out[j] = zero; out[S + j] = zero;
    }
}

// ---------------------------------------------------------------------------
extern "C" void kernel_launch(void* const* d_in, const int* in_sizes, int n_in,
                              void* d_out, int out_size)
{
    (void)in_sizes; (void)n_in; (void)out_size;
    const float* x  = (const float*)d_in[0];
    const float* Wq = (const float*)d_in[1];
    const float* Wk = (const float*)d_in[2];
    const float* Wv = (const float*)d_in[3];
    float* out = (float*)d_out;

    __nv_bfloat16 *x3, *wqt, *wkt, *wvt, *q3, *k3, *vt3, *a3;
    float *vf, *s;
    cudaGetSymbolAddress((void**)&x3,  g_x3);
    cudaGetSymbolAddress((void**)&wqt, g_wqt);
    cudaGetSymbolAddress((void**)&wkt, g_wkt);
    cudaGetSymbolAddress((void**)&wvt, g_wvt);
    cudaGetSymbolAddress((void**)&q3,  g_q3);
    cudaGetSymbolAddress((void**)&k3,  g_k3);
    cudaGetSymbolAddress((void**)&vf,  g_vf);
    cudaGetSymbolAddress((void**)&vt3, g_vt3);
    cudaGetSymbolAddress((void**)&s,   g_s);
    cudaGetSymbolAddress((void**)&a3,  g_a3);

    cudaFuncSetAttribute(gemm_mma, cudaFuncAttributeMaxDynamicSharedMemorySize, GEMM_SMEM);

    const int B = BB, S = SS, D = DD;
    const long long MS = (long long)B * S;   // 8192

    // 1) operand conversion
    conv_split2<<<(int)(MS * D / 256), 256>>>(x, x3, D);
    {
        dim3 tg(D / 32, D / 32, 1);
        transposeY2<<<tg, 256>>>(Wq, wqt, D, D, 0, 0);
        transposeY2<<<tg, 256>>>(Wk, wkt, D, D, 0, 0);
        transposeY2<<<tg, 256>>>(Wv, wvt, D, D, 0, 0);
    }

    // 2) QKV projections [8192 x 1024, K=1024]; q/k epilogue fuses bf16 split
    {
        dim3 gg(D / 128, (int)(MS / 128), 1);
        gemm_mma<<<gg, 128, GEMM_SMEM>>>(x3, wqt, q3, D, D, D / 32,
                                         0, D, 0, 0, 0, D, 0, 0, 0, 0, 1);
        gemm_mma<<<gg, 128, GEMM_SMEM>>>(x3, wkt, k3, D, D, D / 32,
                                         0, D, 0, 0, 0, D, 0, 0, 0, 0, 1);
        gemm_mma<<<gg, 128, GEMM_SMEM>>>(x3, wvt, vf, D, D, D / 32,
                                         0, D, 0, 0, 0, D, 0, 0, 0, 0, 0);
    }

    // 3) transpose-split v
    {
        dim3 tg(D / 32, S / 32, B);
        transposeY2<<<tg, 256>>>(vf, vt3, S, D,
                                 (long long)S * D, (long long)D * 2 * S);
    }

    // 4) scores = Q K^T per batch, causal tile skip
    {
        dim3 gg(S / 128, S / 128, B);
        gemm_mma<<<gg, 128, GEMM_SMEM>>>(q3, k3, s, S, D, D / 32,
                                         0, D, 0, 0, 0, D,
                                         (long long)S * 2 * D, (long long)S * 2 * D,
                                         (long long)S * S, 1, 0);
    }

    // 5) softmax -> split bf16 attn
    softmax2<<<B * S, 256>>>(s, a3, S, 0.03125f);

    // 6) out = attn @ V per batch, K clamped at the diagonal block
    {
        dim3 gg(D / 128, S / 128, B);
        gemm_mma<<<gg, 128, GEMM_SMEM>>>(a3, vt3, out, D, S, S / 32,
                                         0, S, 0, 0, 0, S,
                                         (long long)S * 2 * S, (long long)D * 2 * S,
                                         (long long)S * D, 2, 0);
    }
}